// round 16
// baseline (speedup 1.0000x reference)
#include <cuda_runtime.h>
#include <cuda_fp16.h>
#include <math.h>
#include <stdint.h>

#define DIMM 4096
#define HEADD 128
#define NHQ 32
#define NHKV 8
#define HIDDEN 11008
#define BATCH 32
#define MAXSEQ 2048
#define STARTPOS 1024
#define SEQL (STARTPOS + 1)
#define EPS 1e-5f
#define NCH 8
#define CHL 128

// ---------------- PTX helpers (baseline PTX only) ----------------
__device__ __forceinline__ uint32_t s2u(const void* p) {
    uint32_t a;
    asm("{ .reg .u64 t; cvta.to.shared.u64 t, %1; cvt.u32.u64 %0, t; }" : "=r"(a) : "l"(p));
    return a;
}
__device__ __forceinline__ void ldm_x4(uint32_t* r, uint32_t a) {
    asm volatile("ldmatrix.sync.aligned.m8n8.x4.shared.b16 {%0,%1,%2,%3}, [%4];"
                 : "=r"(r[0]), "=r"(r[1]), "=r"(r[2]), "=r"(r[3]) : "r"(a));
}
__device__ __forceinline__ void ldm_x4t(uint32_t* r, uint32_t a) {
    asm volatile("ldmatrix.sync.aligned.m8n8.x4.trans.shared.b16 {%0,%1,%2,%3}, [%4];"
                 : "=r"(r[0]), "=r"(r[1]), "=r"(r[2]), "=r"(r[3]) : "r"(a));
}
__device__ __forceinline__ void mmah(float* c, const uint32_t* a, const uint32_t* b) {
    asm volatile(
        "mma.sync.aligned.m16n8k16.row.col.f32.f16.f16.f32 "
        "{%0,%1,%2,%3}, {%4,%5,%6,%7}, {%8,%9}, {%0,%1,%2,%3};"
        : "+f"(c[0]), "+f"(c[1]), "+f"(c[2]), "+f"(c[3])
        : "r"(a[0]), "r"(a[1]), "r"(a[2]), "r"(a[3]), "r"(b[0]), "r"(b[1]));
}
__device__ __forceinline__ uint32_t f16pack(float a, float b) {
    __half2 h = __floats2half2_rn(a, b);
    return *reinterpret_cast<uint32_t*>(&h);
}

// ---------------- scratch ----------------
__device__ __align__(16) __half g_xh[BATCH * DIMM];
__device__ __align__(16) __half g_aoh[BATCH * DIMM];
__device__ __align__(16) __half g_h2h[BATCH * DIMM];
__device__ __align__(16) __half g_gh[BATCH * HIDDEN];
__device__ __align__(16) float g_q[BATCH * NHQ * HEADD];
__device__ __align__(16) float g_knew[BATCH * NHKV * HEADD];
__device__ __align__(16) float g_vnew[BATCH * NHKV * HEADD];
__device__ __align__(16) float g_res2[BATCH * DIMM];
__device__ __align__(16) float g_P1[3538944];   // 27 x 4096 x 32 / 18 x 6144 x 32
__device__ __align__(16) float g_P2[1761280];   // 5 x 11008 x 32
__device__ __align__(16) float g_apart[NHKV * BATCH * NCH * 520];

// ---------------- HMMA GEMM core: M=32 x N=256, K64 chunks, fp16, occ-3 ----------------
// smem: A: buf*4608 (32 rows x 144B); B: 9216 + buf*33792 (64 rows x 528B). Total 76800.
#define BPITCH 528
#define GSMEM 76800

__device__ __forceinline__ void gemm_core(
    const __half* __restrict__ XH,
    int Ktot, const float* __restrict__ W, int ldW,
    float* __restrict__ Pout, int s, int nsplit, char* smem, uint32_t sb)
{
    int tid = threadIdx.x, wid = tid >> 5, lane = tid & 31;
    int chunks = Ktot >> 6;
    int c0 = (chunks * s) / nsplit, c1 = (chunks * (s + 1)) / nsplit;
    int nch = c1 - c0;

    float acc[2][4][4];
    #pragma unroll
    for (int t = 0; t < 2; t++)
        #pragma unroll
        for (int u = 0; u < 4; u++)
            #pragma unroll
            for (int i = 0; i < 4; i++) acc[t][u][i] = 0.f;

    int arow = tid >> 3, aseg = tid & 7;
    int bcol = (tid & 31) * 8, brow0 = tid >> 5;

    uint4 AHr;
    float4 Br[4];   // one quarter: 2 rows x 8 floats

    auto GLOADA = [&](int c) {
        int kg = (c0 + c) << 6;
        AHr = *(const uint4*)(XH + (size_t)arow * Ktot + kg + aseg * 8);
    };
    auto GLOADB = [&](int c, int q) {
        int kg = (c0 + c) << 6;
        #pragma unroll
        for (int p = 0; p < 2; p++) {
            int row = brow0 + (q * 2 + p) * 8;
            const float* wp = W + (size_t)(kg + row) * ldW + bcol;
            Br[2 * p]     = *(const float4*)wp;
            Br[2 * p + 1] = *(const float4*)(wp + 4);
        }
    };
    auto GSTOREA = [&](int buf) {
        *(uint4*)(smem + buf * 4608 + arow * 144 + aseg * 16) = AHr;
    };
    auto GSTOREB = [&](int buf, int q) {
        #pragma unroll
        for (int p = 0; p < 2; p++) {
            int row = brow0 + (q * 2 + p) * 8;
            uint4 qq;
            qq.x = f16pack(Br[2 * p].x, Br[2 * p].y);
            qq.y = f16pack(Br[2 * p].z, Br[2 * p].w);
            qq.z = f16pack(Br[2 * p + 1].x, Br[2 * p + 1].y);
            qq.w = f16pack(Br[2 * p + 1].z, Br[2 * p + 1].w);
            *(uint4*)(smem + 9216 + buf * 33792 + row * BPITCH + bcol * 2) = qq;
        }
    };

    // prologue: fill buf 0
    GLOADA(0);
    #pragma unroll
    for (int q = 0; q < 4; q++) { GLOADB(0, q); GSTOREB(0, q); }
    GSTOREA(0);
    __syncthreads();

    uint32_t a_row = ((lane >> 3) & 1) * 8 + (lane & 7);
    uint32_t a_kk8 = (lane >> 4) * 8;
    uint32_t b_kk  = ((lane >> 3) & 1) * 8 + (lane & 7);
    uint32_t b_nn  = (lane >> 4) * 8;

    for (int c = 0; c < nch; c++) {
        int buf = c & 1, nb = (c + 1) & 1;
        bool more = (c + 1 < nch);
        uint32_t abase = sb + buf * 4608;
        uint32_t bbase = sb + 9216 + buf * 33792 + wid * 64;

        if (more) { GLOADA(c + 1); GLOADB(c + 1, 0); }

        #pragma unroll
        for (int ks = 0; ks < 4; ks++) {
            uint32_t ah[2][4], bf[2][4];
            #pragma unroll
            for (int t = 0; t < 2; t++) {
                uint32_t ad = abase + (t * 16 + a_row) * 144 + (ks * 16 + a_kk8) * 2;
                ldm_x4(ah[t], ad);
            }
            uint32_t bd = bbase + (ks * 16 + b_kk) * BPITCH + b_nn * 2;
            ldm_x4t(bf[0], bd);
            ldm_x4t(bf[1], bd + 32);
            #pragma unroll
            for (int t = 0; t < 2; t++)
                #pragma unroll
                for (int u = 0; u < 4; u++)
                    mmah(acc[t][u], ah[t], &bf[u >> 1][2 * (u & 1)]);
            if (more) {
                if (ks == 0) { GSTOREA(nb); GSTOREB(nb, 0); GLOADB(c + 1, 1); }
                else if (ks == 1) { GSTOREB(nb, 1); GLOADB(c + 1, 2); }
                else if (ks == 2) { GSTOREB(nb, 2); GLOADB(c + 1, 3); }
                else { GSTOREB(nb, 3); }
            }
        }
        __syncthreads();
    }

    // epilogue: stage to smem (pitch 36, 16B-aligned), coalesced writes
    {
        float* st = (float*)smem;
        int g = lane >> 2, tg = lane & 3;
        #pragma unroll
        for (int t = 0; t < 2; t++)
            #pragma unroll
            for (int u = 0; u < 4; u++) {
                int n = wid * 32 + u * 8 + tg * 2;
                int r0 = t * 16 + g;
                st[n * 36 + r0]           = acc[t][u][0];
                st[(n + 1) * 36 + r0]     = acc[t][u][1];
                st[n * 36 + r0 + 8]       = acc[t][u][2];
                st[(n + 1) * 36 + r0 + 8] = acc[t][u][3];
            }
        __syncthreads();
        const float4* src = (const float4*)(st + tid * 36);
        float4* dst = (float4*)(Pout + (size_t)tid * 32);
        #pragma unroll
        for (int j = 0; j < 8; j++) dst[j] = src[j];
    }
}

__global__ void __launch_bounds__(256, 3) gemm_qkv_kernel(
    const __half* __restrict__ XH,
    const float* __restrict__ wq, const float* __restrict__ wk, const float* __restrict__ wv,
    float* __restrict__ P)
{
    extern __shared__ char smem[];
    uint32_t sb = s2u(smem);
    int nbase = blockIdx.x * 256, s = blockIdx.y;
    const float* W; int ld, nloc;
    if (nbase < 4096)      { W = wq; ld = 4096; nloc = nbase; }
    else if (nbase < 5120) { W = wk; ld = 1024; nloc = nbase - 4096; }
    else                   { W = wv; ld = 1024; nloc = nbase - 5120; }
    gemm_core(XH, 4096, W + nloc, ld,
              P + ((size_t)s * 6144 + nbase) * 32, s, 18, smem, sb);
}

__global__ void __launch_bounds__(256, 3) gemm_single_kernel(
    const __half* __restrict__ XH,
    int Ktot, const float* __restrict__ W, int ldW,
    float* __restrict__ P, int PN, int nsplit)
{
    extern __shared__ char smem[];
    uint32_t sb = s2u(smem);
    int nbase = blockIdx.x * 256, s = blockIdx.y;
    gemm_core(XH, Ktot, W + nbase, ldW,
              P + ((size_t)s * PN + nbase) * 32, s, nsplit, smem, sb);
}

__global__ void __launch_bounds__(256, 3) gemm_gate_kernel(
    const __half* __restrict__ XH,
    const float* __restrict__ w1, const float* __restrict__ w3,
    float* __restrict__ P1, float* __restrict__ P2)
{
    extern __shared__ char smem[];
    uint32_t sb = s2u(smem);
    int t = blockIdx.x, s = blockIdx.y;
    if (t < 43) {
        int nbase = t * 256;
        gemm_core(XH, 4096, w1 + nbase, HIDDEN,
                  P1 + ((size_t)s * HIDDEN + nbase) * 32, s, 5, smem, sb);
    } else {
        int nbase = (t - 43) * 256;
        gemm_core(XH, 4096, w3 + nbase, HIDDEN,
                  P2 + ((size_t)s * HIDDEN + nbase) * 32, s, 5, smem, sb);
    }
}

// ---------------- rmsnorm -> fp16 (b-major) ----------------
__global__ void __launch_bounds__(256) rmsnorm_half_kernel(
    const float* __restrict__ x, const float* __restrict__ w,
    __half* __restrict__ yh)
{
    int b = blockIdx.x;
    const float* xr = x + (size_t)b * DIMM;
    __shared__ float red[32];
    float ss = 0.f;
    for (int i = threadIdx.x; i < DIMM; i += 256) { float v = xr[i]; ss += v * v; }
    #pragma unroll
    for (int o = 16; o; o >>= 1) ss += __shfl_xor_sync(0xffffffffu, ss, o);
    if ((threadIdx.x & 31) == 0) red[threadIdx.x >> 5] = ss;
    __syncthreads();
    if (threadIdx.x < 32) {
        float v = (threadIdx.x < 8) ? red[threadIdx.x] : 0.f;
        #pragma unroll
        for (int o = 16; o; o >>= 1) v += __shfl_xor_sync(0xffffffffu, v, o);
        if (threadIdx.x == 0) red[0] = v;
    }
    __syncthreads();
    float inv = 1.0f / (sqrtf(red[0] * (1.0f / DIMM)) + EPS);
    for (int i = threadIdx.x; i < DIMM; i += 256)
        yh[(size_t)b * DIMM + i] = __float2half_rn(w[i] * xr[i] * inv);
}

// ---------------- reduces ----------------
__global__ void __launch_bounds__(256) reduce_qkv_rope_kernel(
    const float* __restrict__ P, const float* __restrict__ fcos, const float* __restrict__ fsin,
    float* __restrict__ q, float* __restrict__ knew, float* __restrict__ vnew, int SK)
{
    int c = threadIdx.x & 31, h = threadIdx.x >> 5;
    int colg = blockIdx.x * 128 + 4 * c;
    float4 a[4];
    #pragma unroll
    for (int cc = 0; cc < 4; cc++) a[cc] = make_float4(0.f, 0.f, 0.f, 0.f);
    for (int kz = 0; kz < SK; kz++) {
        const float* p = P + ((size_t)kz * 6144 + colg) * 32 + h * 4;
        #pragma unroll
        for (int cc = 0; cc < 4; cc++) {
            float4 u = *(const float4*)(p + (size_t)cc * 32);
            a[cc].x += u.x; a[cc].y += u.y; a[cc].z += u.z; a[cc].w += u.w;
        }
    }
    int d0 = colg & 127;
    if (colg < 5120) {
        int i0 = d0 >> 1;
        float c0 = fcos[i0], s0 = fsin[i0];
        float c1 = fcos[i0 + 1], s1 = fsin[i0 + 1];
        float* dst; int head, H;
        if (colg < 4096) { head = colg >> 7; dst = q; H = NHQ; }
        else { head = (colg - 4096) >> 7; dst = knew; H = NHKV; }
        #pragma unroll
        for (int e = 0; e < 4; e++) {
            int b = h * 4 + e;
            float x0 = (e == 0 ? a[0].x : e == 1 ? a[0].y : e == 2 ? a[0].z : a[0].w);
            float x1 = (e == 0 ? a[1].x : e == 1 ? a[1].y : e == 2 ? a[1].z : a[1].w);
            float x2 = (e == 0 ? a[2].x : e == 1 ? a[2].y : e == 2 ? a[2].z : a[2].w);
            float x3 = (e == 0 ? a[3].x : e == 1 ? a[3].y : e == 2 ? a[3].z : a[3].w);
            float* o = dst + ((size_t)b * H + head) * HEADD + d0;
            *(float4*)o = make_float4(x0 * c0 - x1 * s0, x0 * s0 + x1 * c0,
                                      x2 * c1 - x3 * s1, x2 * s1 + x3 * c1);
        }
    } else {
        int g = (colg - 5120) >> 7;
        #pragma unroll
        for (int e = 0; e < 4; e++) {
            int b = h * 4 + e;
            float x0 = (e == 0 ? a[0].x : e == 1 ? a[0].y : e == 2 ? a[0].z : a[0].w);
            float x1 = (e == 0 ? a[1].x : e == 1 ? a[1].y : e == 2 ? a[1].z : a[1].w);
            float x2 = (e == 0 ? a[2].x : e == 1 ? a[2].y : e == 2 ? a[2].z : a[2].w);
            float x3 = (e == 0 ? a[3].x : e == 1 ? a[3].y : e == 2 ? a[3].z : a[3].w);
            float* o = vnew + ((size_t)b * NHKV + g) * HEADD + d0;
            *(float4*)o = make_float4(x0, x1, x2, x3);
        }
    }
}

__global__ void __launch_bounds__(256) reduce_addres_kernel(
    const float* __restrict__ P, const float* __restrict__ res, float* __restrict__ out,
    int N, int SK)
{
    int j = threadIdx.x & 7, nl = threadIdx.x >> 3;
    int n = blockIdx.x * 32 + nl;
    float4 a = make_float4(0.f, 0.f, 0.f, 0.f);
    for (int kz = 0; kz < SK; kz++) {
        float4 u = *(const float4*)(P + ((size_t)kz * N + n) * 32 + j * 4);
        a.x += u.x; a.y += u.y; a.z += u.z; a.w += u.w;
    }
    int b0 = 4 * j;
    out[(size_t)(b0 + 0) * N + n] = a.x + res[(size_t)(b0 + 0) * N + n];
    out[(size_t)(b0 + 1) * N + n] = a.y + res[(size_t)(b0 + 1) * N + n];
    out[(size_t)(b0 + 2) * N + n] = a.z + res[(size_t)(b0 + 2) * N + n];
    out[(size_t)(b0 + 3) * N + n] = a.w + res[(size_t)(b0 + 3) * N + n];
}

__global__ void __launch_bounds__(256) reduce_gate_kernel(
    const float* __restrict__ P1, const float* __restrict__ P2,
    __half* __restrict__ gh, int SK)
{
    __shared__ __align__(16) float s1[128 * 36];
    __shared__ __align__(16) float s2[128 * 36];
    int tid = threadIdx.x;
    int j = tid & 7, nl = tid >> 3;
    int nblk = blockIdx.x * 128;
    #pragma unroll
    for (int p = 0; p < 4; p++) {
        int n_local = p * 32 + nl;
        int n = nblk + n_local;
        float4 a = make_float4(0.f, 0.f, 0.f, 0.f), g3 = a;
        for (int kz = 0; kz < SK; kz++) {
            float4 u = *(const float4*)(P1 + ((size_t)kz * HIDDEN + n) * 32 + j * 4);
            a.x += u.x; a.y += u.y; a.z += u.z; a.w += u.w;
            float4 w = *(const float4*)(P2 + ((size_t)kz * HIDDEN + n) * 32 + j * 4);
            g3.x += w.x; g3.y += w.y; g3.z += w.z; g3.w += w.w;
        }
        *(float4*)(s1 + n_local * 36 + 4 * j) = a;
        *(float4*)(s2 + n_local * 36 + 4 * j) = g3;
    }
    __syncthreads();
    int b = tid & 31, ng = tid >> 5;
    __half hb[16];
    #pragma unroll
    for (int i = 0; i < 16; i++) {
        int n_local = ng * 16 + i;
        float v1 = s1[n_local * 36 + b];
        float v3 = s2[n_local * 36 + b];
        float v = (v1 / (1.f + __expf(-v1))) * v3;
        hb[i] = __float2half_rn(v);
    }
    size_t off = (size_t)b * HIDDEN + nblk + ng * 16;
    *(uint4*)(gh + off) = *(uint4*)hb;
    *(uint4*)(gh + off + 8) = *(uint4*)(hb + 8);
}

// ---------------- attention: split-L x8, merged-shfl scores, float4 V ----------------
__global__ void __launch_bounds__(256) attn_part_kernel(
    const float* __restrict__ cache_k, const float* __restrict__ cache_v,
    const float* __restrict__ q, const float* __restrict__ knew, const float* __restrict__ vnew,
    float* __restrict__ apart)
{
    int g = blockIdx.x, b = blockIdx.y, ch = blockIdx.z;
    int lbase = ch * CHL;
    bool last = (ch == NCH - 1);
    int cs = last ? CHL + 1 : CHL;
    __shared__ __align__(16) float sc[4][136];
    __shared__ __align__(16) float qs[4][HEADD];
    __shared__ float red[8];
    __shared__ __align__(16) float vred[8][4][32][4];
    int tid = threadIdx.x, warp = tid >> 5, lane = tid & 31;
    float* ap = apart + (size_t)((g * 32 + b) * NCH + ch) * 520;

    for (int i = tid; i < 4 * HEADD; i += 256) {
        int r = i >> 7, d = i & 127;
        qs[r][d] = q[((size_t)b * NHQ + (g * 4 + r)) * HEADD + d];
    }
    __syncthreads();
    float ql[4][4];
    #pragma unroll
    for (int r = 0; r < 4; r++) {
        float4 t = *(const float4*)&qs[r][lane * 4];
        ql[r][0] = t.x; ql[r][1] = t.y; ql[r][2] = t.z; ql[r][3] = t.w;
    }
    const float scale = 0.08838834764831845f;
    bool odd1 = (lane & 1), odd2 = (lane & 2);

    #pragma unroll 2
    for (int i = 0; i < CHL / 8; i++) {
        int li = warp + i * 8;
        int l = lbase + li;
        const float* kp = cache_k + (((size_t)b * MAXSEQ + l) * NHKV + g) * HEADD;
        float4 kv = *(const float4*)(kp + lane * 4);
        float p0 = kv.x * ql[0][0] + kv.y * ql[0][1] + kv.z * ql[0][2] + kv.w * ql[0][3];
        float p1 = kv.x * ql[1][0] + kv.y * ql[1][1] + kv.z * ql[1][2] + kv.w * ql[1][3];
        float p2 = kv.x * ql[2][0] + kv.y * ql[2][1] + kv.z * ql[2][2] + kv.w * ql[2][3];
        float p3 = kv.x * ql[3][0] + kv.y * ql[3][1] + kv.z * ql[3][2] + kv.w * ql[3][3];
        float a01 = (odd1 ? p1 : p0) + __shfl_xor_sync(0xffffffffu, odd1 ? p0 : p1, 1);
        float a23 = (odd1 ? p3 : p2) + __shfl_xor_sync(0xffffffffu, odd1 ? p2 : p3, 1);
        float v4 = (odd2 ? a23 : a01) + __shfl_xor_sync(0xffffffffu, odd2 ? a01 : a23, 2);
        v4 += __shfl_xor_sync(0xffffffffu, v4, 4);
        v4 += __shfl_xor_sync(0xffffffffu, v4, 8);
        v4 += __shfl_xor_sync(0xffffffffu, v4, 16);
        if (lane < 4) sc[lane][li] = v4 * scale;
    }
    if (last && warp == 0) {
        const float* kp = knew + ((size_t)b * NHKV + g) * HEADD;
        float4 kv = *(const float4*)(kp + lane * 4);
        float p0 = kv.x * ql[0][0] + kv.y * ql[0][1] + kv.z * ql[0][2] + kv.w * ql[0][3];
        float p1 = kv.x * ql[1][0] + kv.y * ql[1][1] + kv.z * ql[1][2] + kv.w * ql[1][3];
        float p2 = kv.x * ql[2][0] + kv.y * ql[2][1] + kv.z * ql[2][2] + kv.w * ql[2][3];
        float p3 = kv.x * ql[3][0] + kv.y * ql[3][1] + kv.z * ql[3][2] + kv.w * ql[3][3];
        float a01 = (odd1 ? p1 : p0) + __shfl_xor_sync(0xffffffffu, odd1 ? p0 : p1, 1);
        float a23 = (odd1 ? p3 : p2) + __shfl_xor_sync(0xffffffffu, odd1 ? p2 : p3, 1);
        float v4 = (odd2 ? a23 : a01) + __shfl_xor_sync(0xffffffffu, odd2 ? a01 : a23, 2);
        v4 += __shfl_xor_sync(0xffffffffu, v4, 4);
        v4 += __shfl_xor_sync(0xffffffffu, v4, 8);
        v4 += __shfl_xor_sync(0xffffffffu, v4, 16);
        if (lane < 4) sc[lane][CHL] = v4 * scale;
    }
    __syncthreads();

    {
        int r = tid >> 6, t = tid & 63;
        float m = -1e30f;
        for (int li = t; li < cs; li += 64) m = fmaxf(m, sc[r][li]);
        #pragma unroll
        for (int o = 16; o; o >>= 1) m = fmaxf(m, __shfl_xor_sync(0xffffffffu, m, o));
        if (lane == 0) red[warp] = m;
        __syncthreads();
        m = fmaxf(red[2 * r], red[2 * r + 1]);
        float s = 0.f;
        for (int li = t; li < cs; li += 64) {
            float e = __expf(sc[r][li] - m);
            sc[r][li] = e; s += e;
        }
        #pragma unroll
        for (int o = 16; o; o >>= 1) s += __shfl_xor_sync(0xffffffffu, s, o);
        __syncthreads();
        if (lane == 0) red[warp] = s;
        __syncthreads();
        s = red[2 * r] + red[2 * r + 1];
        if (t == 0) { ap[r] = m; ap[4 + r] = s; }
    }
    __syncthreads();

    {
        int quad = tid & 31, sl = tid >> 5;
        float4 a0 = make_float4(0, 0, 0, 0), a1 = a0, a2 = a0, a3 = a0;
        if (!last) {
            #pragma unroll 4
            for (int li = sl; li < CHL; li += 8) {
                const float* vp = cache_v + (((size_t)b * MAXSEQ + lbase + li) * NHKV + g) * HEADD;
                float4 v = *(const float4*)(vp + quad * 4);
                float s0 = sc[0][li], s1 = sc[1][li], s2 = sc[2][li], s3 = sc[3][li];
                a0.x += s0 * v.x; a0.y += s0 * v.y; a0.z += s0 * v.z; a0.w += s0 * v.w;
                a1.x += s1 * v.x; a1.y += s1 * v.y; a1.z += s1 * v.z; a1.w += s1 * v.w;
                a2.x += s2 * v.x; a2.y += s2 * v.y; a2.z += s2 * v.z; a2.w += s2 * v.w;
                a3.x += s3 * v.x; a3.y += s3 * v.y; a3.z += s3 * v.z; a3.w += s3 * v.w;
            }
        } else {
            #pragma unroll 4
            for (int li = sl; li < CHL + 1; li += 8) {
                int l = lbase + li;
                const float* vp = (l < STARTPOS)
                    ? cache_v + (((size_t)b * MAXSEQ + l) * NHKV + g) * HEADD
                    : vnew + ((size_t)b * NHKV + g) * HEADD;
                float4 v = *(const float4*)(vp + quad * 4);
                float s0 = sc[0][li], s1 = sc[1][li], s2 = sc[2][li], s3 = sc[3][li];
                a0.x += s0 * v.x; a0.y += s0 * v.y; a0.z += s0 * v.z; a0.w += s0 * v.w;
                a1.x += s1 * v.x; a1.y += s1 * v.y; a1.z += s1 * v.z; a1.w += s1 * v.w;
                a2.x += s2 * v.x; a2.y += s2 * v.y; a2.z += s2 * v.z; a2.w += s2 * v.w;
                a3.x += s3 * v.x; a3.y += s3 * v.y; a3.z += s3 * v.z; a3.w += s3 * v.w;
            }
        }
        *(float4*)&vred[sl][0][quad][0] = a0;
        *(float4*)&vred[sl][1][quad][0] = a1;
        *(float4*)&vred[sl][2][quad][0] = a2;
        *(float4*)&vred[sl][3][quad][0] = a3;
    }
    __syncthreads();
    if (tid < 128) {
        int head = tid >> 5, quad = tid & 31;
        float4 s = make_float4(0, 0, 0, 0);
        #pragma unroll
        for (int sl = 0; sl < 8; sl++) {
            float4 u = *(const float4*)&vred[sl][head][quad][0];
            s.x += u.x; s.y += u.y; s.z += u.z; s.w += u.w;
        }
        *(float4*)(ap + 8 + head * 128 + quad * 4) = s;
    }
}

__global__ void __launch_bounds__(128) attn_combine_kernel(
    const float* __restrict__ apart, __half* __restrict__ aoh)
{
    int g = blockIdx.x, b = blockIdx.y, d = threadIdx.x;
    const float* base = apart + (size_t)((g * 32 + b) * NCH) * 520;
    #pragma unroll
    for (int r = 0; r < 4; r++) {
        float M = -1e30f;
        #pragma unroll
        for (int c = 0; c < NCH; c++) M = fmaxf(M, base[c * 520 + r]);
        float denom = 0.f, o = 0.f;
        #pragma unroll
        for (int c = 0; c < NCH; c++) {
            float w = __expf(base[c * 520 + r] - M);
            denom += base[c * 520 + 4 + r] * w;
            o += base[c * 520 + 8 + r * 128 + d] * w;
        }
        aoh[(size_t)b * DIMM + (g * 4 + r) * 128 + d] = __float2half_rn(o / denom);
    }
}

// ---------------- launch ----------------
extern "C" void kernel_launch(void* const* d_in, const int* in_sizes, int n_in,
                              void* d_out, int out_size)
{
    const float* x     = (const float*)d_in[0];
    const float* fcos  = (const float*)d_in[2];
    const float* fsin  = (const float*)d_in[3];
    const float* cachek = (const float*)d_in[4];
    const float* cachev = (const float*)d_in[5];
    const float* wq = (const float*)d_in[6];
    const float* wk = (const float*)d_in[7];
    const float* wv = (const float*)d_in[8];
    const float* wo = (const float*)d_in[9];
    const float* w1 = (const float*)d_in[10];
    const float* w2 = (const float*)d_in[11];
    const float* w3 = (const float*)d_in[12];
    const float* anw = (const float*)d_in[13];
    const float* fnw = (const float*)d_in[14];
    float* out = (float*)d_out;

    __half *p_xh, *p_aoh, *p_h2h, *p_gh;
    float *p_q, *p_knew, *p_vnew, *p_res2, *p_P1, *p_P2, *p_apart;
    cudaGetSymbolAddress((void**)&p_xh, g_xh);
    cudaGetSymbolAddress((void**)&p_aoh, g_aoh);
    cudaGetSymbolAddress((void**)&p_h2h, g_h2h);
    cudaGetSymbolAddress((void**)&p_gh, g_gh);
    cudaGetSymbolAddress((void**)&p_q, g_q);
    cudaGetSymbolAddress((void**)&p_knew, g_knew);
    cudaGetSymbolAddress((void**)&p_vnew, g_vnew);
    cudaGetSymbolAddress((void**)&p_res2, g_res2);
    cudaGetSymbolAddress((void**)&p_P1, g_P1);
    cudaGetSymbolAddress((void**)&p_P2, g_P2);
    cudaGetSymbolAddress((void**)&p_apart, g_apart);

    cudaFuncSetAttribute(gemm_qkv_kernel, cudaFuncAttributeMaxDynamicSharedMemorySize, GSMEM);
    cudaFuncSetAttribute(gemm_single_kernel, cudaFuncAttributeMaxDynamicSharedMemorySize, GSMEM);
    cudaFuncSetAttribute(gemm_gate_kernel, cudaFuncAttributeMaxDynamicSharedMemorySize, GSMEM);

    rmsnorm_half_kernel<<<32, 256>>>(x, anw, p_xh);
    gemm_qkv_kernel<<<dim3(24, 18), 256, GSMEM>>>(p_xh, wq, wk, wv, p_P1);
    reduce_qkv_rope_kernel<<<48, 256>>>(p_P1, fcos, fsin, p_q, p_knew, p_vnew, 18);
    attn_part_kernel<<<dim3(8, 32, NCH), 256>>>(cachek, cachev, p_q, p_knew, p_vnew, p_apart);
    attn_combine_kernel<<<dim3(8, 32), 128>>>(p_apart, p_aoh);
    gemm_single_kernel<<<dim3(16, 27), 256, GSMEM>>>(p_aoh, 4096, wo, 4096, p_P1, 4096, 27);
    reduce_addres_kernel<<<128, 256>>>(p_P1, x, p_res2, 4096, 27);
    rmsnorm_half_kernel<<<32, 256>>>(p_res2, fnw, p_h2h);
    gemm_gate_kernel<<<dim3(86, 5), 256, GSMEM>>>(p_h2h, w1, w3, p_P1, p_P2);
    reduce_gate_kernel<<<86, 256>>>(p_P1, p_P2, p_gh, 5);
    gemm_single_kernel<<<dim3(16, 27), 256, GSMEM>>>(p_gh, 11008, w2, 4096, p_P1, 4096, 27);
    reduce_addres_kernel<<<128, 256>>>(p_P1, p_res2, out, 4096, 27);
}

// round 17
// speedup vs baseline: 1.2006x; 1.2006x over previous
#include <cuda_runtime.h>
#include <cuda_fp16.h>
#include <math.h>
#include <stdint.h>

#define DIMM 4096
#define HEADD 128
#define NHQ 32
#define NHKV 8
#define HIDDEN 11008
#define BATCH 32
#define MAXSEQ 2048
#define STARTPOS 1024
#define SEQL (STARTPOS + 1)
#define EPS 1e-5f
#define NCH 8
#define CHL 128

// ---------------- PTX helpers (baseline PTX only) ----------------
__device__ __forceinline__ uint32_t s2u(const void* p) {
    uint32_t a;
    asm("{ .reg .u64 t; cvta.to.shared.u64 t, %1; cvt.u32.u64 %0, t; }" : "=r"(a) : "l"(p));
    return a;
}
__device__ __forceinline__ void ldm_x4(uint32_t* r, uint32_t a) {
    asm volatile("ldmatrix.sync.aligned.m8n8.x4.shared.b16 {%0,%1,%2,%3}, [%4];"
                 : "=r"(r[0]), "=r"(r[1]), "=r"(r[2]), "=r"(r[3]) : "r"(a));
}
__device__ __forceinline__ void ldm_x4t(uint32_t* r, uint32_t a) {
    asm volatile("ldmatrix.sync.aligned.m8n8.x4.trans.shared.b16 {%0,%1,%2,%3}, [%4];"
                 : "=r"(r[0]), "=r"(r[1]), "=r"(r[2]), "=r"(r[3]) : "r"(a));
}
__device__ __forceinline__ void mmah(float* c, const uint32_t* a, const uint32_t* b) {
    asm volatile(
        "mma.sync.aligned.m16n8k16.row.col.f32.f16.f16.f32 "
        "{%0,%1,%2,%3}, {%4,%5,%6,%7}, {%8,%9}, {%0,%1,%2,%3};"
        : "+f"(c[0]), "+f"(c[1]), "+f"(c[2]), "+f"(c[3])
        : "r"(a[0]), "r"(a[1]), "r"(a[2]), "r"(a[3]), "r"(b[0]), "r"(b[1]));
}
__device__ __forceinline__ uint32_t f16pack(float a, float b) {
    __half2 h = __floats2half2_rn(a, b);
    return *reinterpret_cast<uint32_t*>(&h);
}

// ---------------- scratch ----------------
__device__ __align__(16) __half g_xh[BATCH * DIMM];
__device__ __align__(16) __half g_aoh[BATCH * DIMM];
__device__ __align__(16) __half g_h2h[BATCH * DIMM];
__device__ __align__(16) __half g_gh[BATCH * HIDDEN];
__device__ __align__(16) float g_q[BATCH * NHQ * HEADD];
__device__ __align__(16) float g_knew[BATCH * NHKV * HEADD];
__device__ __align__(16) float g_vnew[BATCH * NHKV * HEADD];
__device__ __align__(16) float g_res2[BATCH * DIMM];
__device__ __align__(16) float g_P1[2359296];
__device__ __align__(16) float g_P2[1056768];
__device__ __align__(16) float g_apart[NHKV * BATCH * NCH * 520];

// ---------------- HMMA GEMM core: M=32 x N=256, K64 chunks, fp16 single-pass ----------------
#define BPITCH 528
#define GSMEM 86016

__device__ __forceinline__ void gemm_core(
    const __half* __restrict__ XH,
    int Ktot, const float* __restrict__ W, int ldW,
    float* __restrict__ Pout, int s, int nsplit, char* smem, uint32_t sb)
{
    int tid = threadIdx.x, wid = tid >> 5, lane = tid & 31;
    int chunks = Ktot >> 6;
    int c0 = (chunks * s) / nsplit, c1 = (chunks * (s + 1)) / nsplit;
    int nch = c1 - c0;

    float acc[2][4][4];
    #pragma unroll
    for (int t = 0; t < 2; t++)
        #pragma unroll
        for (int u = 0; u < 4; u++)
            #pragma unroll
            for (int i = 0; i < 4; i++) acc[t][u][i] = 0.f;

    int arow = tid >> 3, aseg = tid & 7;
    int bcol = (tid & 31) * 8, brow0 = tid >> 5;

    uint4 AHr;
    float4 Br[8];

    auto GLOADA = [&](int c) {
        int kg = (c0 + c) << 6;
        AHr = *(const uint4*)(XH + (size_t)arow * Ktot + kg + aseg * 8);
    };
    auto GLOADB = [&](int c, int half) {
        int kg = (c0 + c) << 6;
        #pragma unroll
        for (int p = 0; p < 4; p++) {
            int row = brow0 + (half * 4 + p) * 8;
            const float* wp = W + (size_t)(kg + row) * ldW + bcol;
            Br[2 * p]     = *(const float4*)wp;
            Br[2 * p + 1] = *(const float4*)(wp + 4);
        }
    };
    auto GSTOREA = [&](int buf) {
        *(uint4*)(smem + buf * 9216 + arow * 144 + aseg * 16) = AHr;
    };
    auto GSTOREB = [&](int buf, int half) {
        #pragma unroll
        for (int p = 0; p < 4; p++) {
            int row = brow0 + (half * 4 + p) * 8;
            uint4 q;
            q.x = f16pack(Br[2 * p].x, Br[2 * p].y);
            q.y = f16pack(Br[2 * p].z, Br[2 * p].w);
            q.z = f16pack(Br[2 * p + 1].x, Br[2 * p + 1].y);
            q.w = f16pack(Br[2 * p + 1].z, Br[2 * p + 1].w);
            *(uint4*)(smem + 18432 + buf * 33792 + row * BPITCH + bcol * 2) = q;
        }
    };

    GLOADA(0); GLOADB(0, 0);
    GSTOREA(0); GSTOREB(0, 0);
    GLOADB(0, 1); GSTOREB(0, 1);
    __syncthreads();

    uint32_t a_row = ((lane >> 3) & 1) * 8 + (lane & 7);
    uint32_t a_kk8 = (lane >> 4) * 8;
    uint32_t b_kk  = ((lane >> 3) & 1) * 8 + (lane & 7);
    uint32_t b_nn  = (lane >> 4) * 8;

    for (int c = 0; c < nch; c++) {
        int buf = c & 1, nb = (c + 1) & 1;
        bool more = (c + 1 < nch);
        if (more) { GLOADA(c + 1); GLOADB(c + 1, 0); }

        uint32_t abase = sb + buf * 9216;
        uint32_t bbase = sb + 18432 + buf * 33792 + wid * 64;

        #pragma unroll
        for (int ks = 0; ks < 2; ks++) {
            uint32_t ah[2][4], bf[2][4];
            #pragma unroll
            for (int t = 0; t < 2; t++) {
                uint32_t ad = abase + (t * 16 + a_row) * 144 + (ks * 16 + a_kk8) * 2;
                ldm_x4(ah[t], ad);
            }
            uint32_t bd = bbase + (ks * 16 + b_kk) * BPITCH + b_nn * 2;
            ldm_x4t(bf[0], bd);
            ldm_x4t(bf[1], bd + 32);
            #pragma unroll
            for (int t = 0; t < 2; t++)
                #pragma unroll
                for (int u = 0; u < 4; u++)
                    mmah(acc[t][u], ah[t], &bf[u >> 1][2 * (u & 1)]);
        }
        if (more) { GSTOREA(nb); GSTOREB(nb, 0); GLOADB(c + 1, 1); }
        #pragma unroll
        for (int ks = 2; ks < 4; ks++) {
            uint32_t ah[2][4], bf[2][4];
            #pragma unroll
            for (int t = 0; t < 2; t++) {
                uint32_t ad = abase + (t * 16 + a_row) * 144 + (ks * 16 + a_kk8) * 2;
                ldm_x4(ah[t], ad);
            }
            uint32_t bd = bbase + (ks * 16 + b_kk) * BPITCH + b_nn * 2;
            ldm_x4t(bf[0], bd);
            ldm_x4t(bf[1], bd + 32);
            #pragma unroll
            for (int t = 0; t < 2; t++)
                #pragma unroll
                for (int u = 0; u < 4; u++)
                    mmah(acc[t][u], ah[t], &bf[u >> 1][2 * (u & 1)]);
        }
        if (more) GSTOREB(nb, 1);
        __syncthreads();
    }

    {
        float* st = (float*)smem;
        int g = lane >> 2, tg = lane & 3;
        #pragma unroll
        for (int t = 0; t < 2; t++)
            #pragma unroll
            for (int u = 0; u < 4; u++) {
                int n = wid * 32 + u * 8 + tg * 2;
                int r0 = t * 16 + g;
                st[n * 36 + r0]           = acc[t][u][0];
                st[(n + 1) * 36 + r0]     = acc[t][u][1];
                st[n * 36 + r0 + 8]       = acc[t][u][2];
                st[(n + 1) * 36 + r0 + 8] = acc[t][u][3];
            }
        __syncthreads();
        const float4* src = (const float4*)(st + tid * 36);
        float4* dst = (float4*)(Pout + (size_t)tid * 32);
        #pragma unroll
        for (int j = 0; j < 8; j++) dst[j] = src[j];
    }
}

__global__ void __launch_bounds__(256, 2) gemm_qkv_kernel(
    const __half* __restrict__ XH,
    const float* __restrict__ wq, const float* __restrict__ wk, const float* __restrict__ wv,
    float* __restrict__ P)
{
    extern __shared__ char smem[];
    uint32_t sb = s2u(smem);
    int nbase = blockIdx.x * 256, s = blockIdx.y;
    const float* W; int ld, nloc;
    if (nbase < 4096)      { W = wq; ld = 4096; nloc = nbase; }
    else if (nbase < 5120) { W = wk; ld = 1024; nloc = nbase - 4096; }
    else                   { W = wv; ld = 1024; nloc = nbase - 5120; }
    gemm_core(XH, 4096, W + nloc, ld,
              P + ((size_t)s * 6144 + nbase) * 32, s, 12, smem, sb);
}

__global__ void __launch_bounds__(256, 2) gemm_single_kernel(
    const __half* __restrict__ XH,
    int Ktot, const float* __restrict__ W, int ldW,
    float* __restrict__ P, int PN, int nsplit)
{
    extern __shared__ char smem[];
    uint32_t sb = s2u(smem);
    int nbase = blockIdx.x * 256, s = blockIdx.y;
    gemm_core(XH, Ktot, W + nbase, ldW,
              P + ((size_t)s * PN + nbase) * 32, s, nsplit, smem, sb);
}

__global__ void __launch_bounds__(256, 2) gemm_gate_kernel(
    const __half* __restrict__ XH,
    const float* __restrict__ w1, const float* __restrict__ w3,
    float* __restrict__ P1, float* __restrict__ P2)
{
    extern __shared__ char smem[];
    uint32_t sb = s2u(smem);
    int t = blockIdx.x, s = blockIdx.y;
    if (t < 43) {
        int nbase = t * 256;
        gemm_core(XH, 4096, w1 + nbase, HIDDEN,
                  P1 + ((size_t)s * HIDDEN + nbase) * 32, s, 3, smem, sb);
    } else {
        int nbase = (t - 43) * 256;
        gemm_core(XH, 4096, w3 + nbase, HIDDEN,
                  P2 + ((size_t)s * HIDDEN + nbase) * 32, s, 3, smem, sb);
    }
}

// ---------------- rmsnorm -> fp16 (b-major) ----------------
__global__ void __launch_bounds__(256) rmsnorm_half_kernel(
    const float* __restrict__ x, const float* __restrict__ w,
    __half* __restrict__ yh)
{
    int b = blockIdx.x;
    const float* xr = x + (size_t)b * DIMM;
    __shared__ float red[32];
    float ss = 0.f;
    for (int i = threadIdx.x; i < DIMM; i += 256) { float v = xr[i]; ss += v * v; }
    #pragma unroll
    for (int o = 16; o; o >>= 1) ss += __shfl_xor_sync(0xffffffffu, ss, o);
    if ((threadIdx.x & 31) == 0) red[threadIdx.x >> 5] = ss;
    __syncthreads();
    if (threadIdx.x < 32) {
        float v = (threadIdx.x < 8) ? red[threadIdx.x] : 0.f;
        #pragma unroll
        for (int o = 16; o; o >>= 1) v += __shfl_xor_sync(0xffffffffu, v, o);
        if (threadIdx.x == 0) red[0] = v;
    }
    __syncthreads();
    float inv = 1.0f / (sqrtf(red[0] * (1.0f / DIMM)) + EPS);
    for (int i = threadIdx.x; i < DIMM; i += 256)
        yh[(size_t)b * DIMM + i] = __float2half_rn(w[i] * xr[i] * inv);
}

// ---------------- reduces ----------------
__global__ void __launch_bounds__(256) reduce_qkv_rope_kernel(
    const float* __restrict__ P, const float* __restrict__ fcos, const float* __restrict__ fsin,
    float* __restrict__ q, float* __restrict__ knew, float* __restrict__ vnew, int SK)
{
    int c = threadIdx.x & 31, h = threadIdx.x >> 5;
    int colg = blockIdx.x * 128 + 4 * c;
    float4 a[4];
    #pragma unroll
    for (int cc = 0; cc < 4; cc++) a[cc] = make_float4(0.f, 0.f, 0.f, 0.f);
    for (int kz = 0; kz < SK; kz++) {
        const float* p = P + ((size_t)kz * 6144 + colg) * 32 + h * 4;
        #pragma unroll
        for (int cc = 0; cc < 4; cc++) {
            float4 u = *(const float4*)(p + (size_t)cc * 32);
            a[cc].x += u.x; a[cc].y += u.y; a[cc].z += u.z; a[cc].w += u.w;
        }
    }
    int d0 = colg & 127;
    if (colg < 5120) {
        int i0 = d0 >> 1;
        float c0 = fcos[i0], s0 = fsin[i0];
        float c1 = fcos[i0 + 1], s1 = fsin[i0 + 1];
        float* dst; int head, H;
        if (colg < 4096) { head = colg >> 7; dst = q; H = NHQ; }
        else { head = (colg - 4096) >> 7; dst = knew; H = NHKV; }
        #pragma unroll
        for (int e = 0; e < 4; e++) {
            int b = h * 4 + e;
            float x0 = (e == 0 ? a[0].x : e == 1 ? a[0].y : e == 2 ? a[0].z : a[0].w);
            float x1 = (e == 0 ? a[1].x : e == 1 ? a[1].y : e == 2 ? a[1].z : a[1].w);
            float x2 = (e == 0 ? a[2].x : e == 1 ? a[2].y : e == 2 ? a[2].z : a[2].w);
            float x3 = (e == 0 ? a[3].x : e == 1 ? a[3].y : e == 2 ? a[3].z : a[3].w);
            float* o = dst + ((size_t)b * H + head) * HEADD + d0;
            *(float4*)o = make_float4(x0 * c0 - x1 * s0, x0 * s0 + x1 * c0,
                                      x2 * c1 - x3 * s1, x2 * s1 + x3 * c1);
        }
    } else {
        int g = (colg - 5120) >> 7;
        #pragma unroll
        for (int e = 0; e < 4; e++) {
            int b = h * 4 + e;
            float x0 = (e == 0 ? a[0].x : e == 1 ? a[0].y : e == 2 ? a[0].z : a[0].w);
            float x1 = (e == 0 ? a[1].x : e == 1 ? a[1].y : e == 2 ? a[1].z : a[1].w);
            float x2 = (e == 0 ? a[2].x : e == 1 ? a[2].y : e == 2 ? a[2].z : a[2].w);
            float x3 = (e == 0 ? a[3].x : e == 1 ? a[3].y : e == 2 ? a[3].z : a[3].w);
            float* o = vnew + ((size_t)b * NHKV + g) * HEADD + d0;
            *(float4*)o = make_float4(x0, x1, x2, x3);
        }
    }
}

__global__ void __launch_bounds__(256) reduce_addres_kernel(
    const float* __restrict__ P, const float* __restrict__ res, float* __restrict__ out,
    int N, int SK)
{
    int j = threadIdx.x & 7, nl = threadIdx.x >> 3;
    int n = blockIdx.x * 32 + nl;
    float4 a = make_float4(0.f, 0.f, 0.f, 0.f);
    for (int kz = 0; kz < SK; kz++) {
        float4 u = *(const float4*)(P + ((size_t)kz * N + n) * 32 + j * 4);
        a.x += u.x; a.y += u.y; a.z += u.z; a.w += u.w;
    }
    int b0 = 4 * j;
    out[(size_t)(b0 + 0) * N + n] = a.x + res[(size_t)(b0 + 0) * N + n];
    out[(size_t)(b0 + 1) * N + n] = a.y + res[(size_t)(b0 + 1) * N + n];
    out[(size_t)(b0 + 2) * N + n] = a.z + res[(size_t)(b0 + 2) * N + n];
    out[(size_t)(b0 + 3) * N + n] = a.w + res[(size_t)(b0 + 3) * N + n];
}

__global__ void __launch_bounds__(256) reduce_gate_kernel(
    const float* __restrict__ P1, const float* __restrict__ P2,
    __half* __restrict__ gh, int SK)
{
    __shared__ __align__(16) float s1[128 * 36];
    __shared__ __align__(16) float s2[128 * 36];
    int tid = threadIdx.x;
    int j = tid & 7, nl = tid >> 3;
    int nblk = blockIdx.x * 128;
    #pragma unroll
    for (int p = 0; p < 4; p++) {
        int n_local = p * 32 + nl;
        int n = nblk + n_local;
        float4 a = make_float4(0.f, 0.f, 0.f, 0.f), g3 = a;
        for (int kz = 0; kz < SK; kz++) {
            float4 u = *(const float4*)(P1 + ((size_t)kz * HIDDEN + n) * 32 + j * 4);
            a.x += u.x; a.y += u.y; a.z += u.z; a.w += u.w;
            float4 w = *(const float4*)(P2 + ((size_t)kz * HIDDEN + n) * 32 + j * 4);
            g3.x += w.x; g3.y += w.y; g3.z += w.z; g3.w += w.w;
        }
        *(float4*)(s1 + n_local * 36 + 4 * j) = a;
        *(float4*)(s2 + n_local * 36 + 4 * j) = g3;
    }
    __syncthreads();
    int b = tid & 31, ng = tid >> 5;
    __half hb[16];
    #pragma unroll
    for (int i = 0; i < 16; i++) {
        int n_local = ng * 16 + i;
        float v1 = s1[n_local * 36 + b];
        float v3 = s2[n_local * 36 + b];
        float v = (v1 / (1.f + __expf(-v1))) * v3;
        hb[i] = __float2half_rn(v);
    }
    size_t off = (size_t)b * HIDDEN + nblk + ng * 16;
    *(uint4*)(gh + off) = *(uint4*)hb;
    *(uint4*)(gh + off + 8) = *(uint4*)(hb + 8);
}

// ---------------- attention: split-L x8, merged-shfl scores, float4 V ----------------
__global__ void __launch_bounds__(256) attn_part_kernel(
    const float* __restrict__ cache_k, const float* __restrict__ cache_v,
    const float* __restrict__ q, const float* __restrict__ knew, const float* __restrict__ vnew,
    float* __restrict__ apart)
{
    int g = blockIdx.x, b = blockIdx.y, ch = blockIdx.z;
    int lbase = ch * CHL;
    bool last = (ch == NCH - 1);
    int cs = last ? CHL + 1 : CHL;
    __shared__ __align__(16) float sc[4][136];
    __shared__ __align__(16) float qs[4][HEADD];
    __shared__ float red[8];
    __shared__ __align__(16) float vred[8][4][32][4];
    int tid = threadIdx.x, warp = tid >> 5, lane = tid & 31;
    float* ap = apart + (size_t)((g * 32 + b) * NCH + ch) * 520;

    for (int i = tid; i < 4 * HEADD; i += 256) {
        int r = i >> 7, d = i & 127;
        qs[r][d] = q[((size_t)b * NHQ + (g * 4 + r)) * HEADD + d];
    }
    __syncthreads();
    float ql[4][4];
    #pragma unroll
    for (int r = 0; r < 4; r++) {
        float4 t = *(const float4*)&qs[r][lane * 4];
        ql[r][0] = t.x; ql[r][1] = t.y; ql[r][2] = t.z; ql[r][3] = t.w;
    }
    const float scale = 0.08838834764831845f;
    bool odd1 = (lane & 1), odd2 = (lane & 2);

    #pragma unroll 2
    for (int i = 0; i < CHL / 8; i++) {
        int li = warp + i * 8;
        int l = lbase + li;
        const float* kp = cache_k + (((size_t)b * MAXSEQ + l) * NHKV + g) * HEADD;
        float4 kv = *(const float4*)(kp + lane * 4);
        float p0 = kv.x * ql[0][0] + kv.y * ql[0][1] + kv.z * ql[0][2] + kv.w * ql[0][3];
        float p1 = kv.x * ql[1][0] + kv.y * ql[1][1] + kv.z * ql[1][2] + kv.w * ql[1][3];
        float p2 = kv.x * ql[2][0] + kv.y * ql[2][1] + kv.z * ql[2][2] + kv.w * ql[2][3];
        float p3 = kv.x * ql[3][0] + kv.y * ql[3][1] + kv.z * ql[3][2] + kv.w * ql[3][3];
        float a01 = (odd1 ? p1 : p0) + __shfl_xor_sync(0xffffffffu, odd1 ? p0 : p1, 1);
        float a23 = (odd1 ? p3 : p2) + __shfl_xor_sync(0xffffffffu, odd1 ? p2 : p3, 1);
        float v4 = (odd2 ? a23 : a01) + __shfl_xor_sync(0xffffffffu, odd2 ? a01 : a23, 2);
        v4 += __shfl_xor_sync(0xffffffffu, v4, 4);
        v4 += __shfl_xor_sync(0xffffffffu, v4, 8);
        v4 += __shfl_xor_sync(0xffffffffu, v4, 16);
        if (lane < 4) sc[lane][li] = v4 * scale;
    }
    if (last && warp == 0) {
        const float* kp = knew + ((size_t)b * NHKV + g) * HEADD;
        float4 kv = *(const float4*)(kp + lane * 4);
        float p0 = kv.x * ql[0][0] + kv.y * ql[0][1] + kv.z * ql[0][2] + kv.w * ql[0][3];
        float p1 = kv.x * ql[1][0] + kv.y * ql[1][1] + kv.z * ql[1][2] + kv.w * ql[1][3];
        float p2 = kv.x * ql[2][0] + kv.y * ql[2][1] + kv.z * ql[2][2] + kv.w * ql[2][3];
        float p3 = kv.x * ql[3][0] + kv.y * ql[3][1] + kv.z * ql[3][2] + kv.w * ql[3][3];
        float a01 = (odd1 ? p1 : p0) + __shfl_xor_sync(0xffffffffu, odd1 ? p0 : p1, 1);
        float a23 = (odd1 ? p3 : p2) + __shfl_xor_sync(0xffffffffu, odd1 ? p2 : p3, 1);
        float v4 = (odd2 ? a23 : a01) + __shfl_xor_sync(0xffffffffu, odd2 ? a01 : a23, 2);
        v4 += __shfl_xor_sync(0xffffffffu, v4, 4);
        v4 += __shfl_xor_sync(0xffffffffu, v4, 8);
        v4 += __shfl_xor_sync(0xffffffffu, v4, 16);
        if (lane < 4) sc[lane][CHL] = v4 * scale;
    }
    __syncthreads();

    {
        int r = tid >> 6, t = tid & 63;
        float m = -1e30f;
        for (int li = t; li < cs; li += 64) m = fmaxf(m, sc[r][li]);
        #pragma unroll
        for (int o = 16; o; o >>= 1) m = fmaxf(m, __shfl_xor_sync(0xffffffffu, m, o));
        if (lane == 0) red[warp] = m;
        __syncthreads();
        m = fmaxf(red[2 * r], red[2 * r + 1]);
        float s = 0.f;
        for (int li = t; li < cs; li += 64) {
            float e = __expf(sc[r][li] - m);
            sc[r][li] = e; s += e;
        }
        #pragma unroll
        for (int o = 16; o; o >>= 1) s += __shfl_xor_sync(0xffffffffu, s, o);
        __syncthreads();
        if (lane == 0) red[warp] = s;
        __syncthreads();
        s = red[2 * r] + red[2 * r + 1];
        if (t == 0) { ap[r] = m; ap[4 + r] = s; }
    }
    __syncthreads();

    {
        int quad = tid & 31, sl = tid >> 5;
        float4 a0 = make_float4(0, 0, 0, 0), a1 = a0, a2 = a0, a3 = a0;
        if (!last) {
            #pragma unroll 4
            for (int li = sl; li < CHL; li += 8) {
                const float* vp = cache_v + (((size_t)b * MAXSEQ + lbase + li) * NHKV + g) * HEADD;
                float4 v = *(const float4*)(vp + quad * 4);
                float s0 = sc[0][li], s1 = sc[1][li], s2 = sc[2][li], s3 = sc[3][li];
                a0.x += s0 * v.x; a0.y += s0 * v.y; a0.z += s0 * v.z; a0.w += s0 * v.w;
                a1.x += s1 * v.x; a1.y += s1 * v.y; a1.z += s1 * v.z; a1.w += s1 * v.w;
                a2.x += s2 * v.x; a2.y += s2 * v.y; a2.z += s2 * v.z; a2.w += s2 * v.w;
                a3.x += s3 * v.x; a3.y += s3 * v.y; a3.z += s3 * v.z; a3.w += s3 * v.w;
            }
        } else {
            #pragma unroll 4
            for (int li = sl; li < CHL + 1; li += 8) {
                int l = lbase + li;
                const float* vp = (l < STARTPOS)
                    ? cache_v + (((size_t)b * MAXSEQ + l) * NHKV + g) * HEADD
                    : vnew + ((size_t)b * NHKV + g) * HEADD;
                float4 v = *(const float4*)(vp + quad * 4);
                float s0 = sc[0][li], s1 = sc[1][li], s2 = sc[2][li], s3 = sc[3][li];
                a0.x += s0 * v.x; a0.y += s0 * v.y; a0.z += s0 * v.z; a0.w += s0 * v.w;
                a1.x += s1 * v.x; a1.y += s1 * v.y; a1.z += s1 * v.z; a1.w += s1 * v.w;
                a2.x += s2 * v.x; a2.y += s2 * v.y; a2.z += s2 * v.z; a2.w += s2 * v.w;
                a3.x += s3 * v.x; a3.y += s3 * v.y; a3.z += s3 * v.z; a3.w += s3 * v.w;
            }
        }
        *(float4*)&vred[sl][0][quad][0] = a0;
        *(float4*)&vred[sl][1][quad][0] = a1;
        *(float4*)&vred[sl][2][quad][0] = a2;
        *(float4*)&vred[sl][3][quad][0] = a3;
    }
    __syncthreads();
    if (tid < 128) {
        int head = tid >> 5, quad = tid & 31;
        float4 s = make_float4(0, 0, 0, 0);
        #pragma unroll
        for (int sl = 0; sl < 8; sl++) {
            float4 u = *(const float4*)&vred[sl][head][quad][0];
            s.x += u.x; s.y += u.y; s.z += u.z; s.w += u.w;
        }
        *(float4*)(ap + 8 + head * 128 + quad * 4) = s;
    }
}

__global__ void __launch_bounds__(128) attn_combine_kernel(
    const float* __restrict__ apart, __half* __restrict__ aoh)
{
    int g = blockIdx.x, b = blockIdx.y, d = threadIdx.x;
    const float* base = apart + (size_t)((g * 32 + b) * NCH) * 520;
    #pragma unroll
    for (int r = 0; r < 4; r++) {
        float M = -1e30f;
        #pragma unroll
        for (int c = 0; c < NCH; c++) M = fmaxf(M, base[c * 520 + r]);
        float denom = 0.f, o = 0.f;
        #pragma unroll
        for (int c = 0; c < NCH; c++) {
            float w = __expf(base[c * 520 + r] - M);
            denom += base[c * 520 + 4 + r] * w;
            o += base[c * 520 + 8 + r * 128 + d] * w;
        }
        aoh[(size_t)b * DIMM + (g * 4 + r) * 128 + d] = __float2half_rn(o / denom);
    }
}

// ---------------- launch ----------------
extern "C" void kernel_launch(void* const* d_in, const int* in_sizes, int n_in,
                              void* d_out, int out_size)
{
    const float* x     = (const float*)d_in[0];
    const float* fcos  = (const float*)d_in[2];
    const float* fsin  = (const float*)d_in[3];
    const float* cachek = (const float*)d_in[4];
    const float* cachev = (const float*)d_in[5];
    const float* wq = (const float*)d_in[6];
    const float* wk = (const float*)d_in[7];
    const float* wv = (const float*)d_in[8];
    const float* wo = (const float*)d_in[9];
    const float* w1 = (const float*)d_in[10];
    const float* w2 = (const float*)d_in[11];
    const float* w3 = (const float*)d_in[12];
    const float* anw = (const float*)d_in[13];
    const float* fnw = (const float*)d_in[14];
    float* out = (float*)d_out;

    __half *p_xh, *p_aoh, *p_h2h, *p_gh;
    float *p_q, *p_knew, *p_vnew, *p_res2, *p_P1, *p_P2, *p_apart;
    cudaGetSymbolAddress((void**)&p_xh, g_xh);
    cudaGetSymbolAddress((void**)&p_aoh, g_aoh);
    cudaGetSymbolAddress((void**)&p_h2h, g_h2h);
    cudaGetSymbolAddress((void**)&p_gh, g_gh);
    cudaGetSymbolAddress((void**)&p_q, g_q);
    cudaGetSymbolAddress((void**)&p_knew, g_knew);
    cudaGetSymbolAddress((void**)&p_vnew, g_vnew);
    cudaGetSymbolAddress((void**)&p_res2, g_res2);
    cudaGetSymbolAddress((void**)&p_P1, g_P1);
    cudaGetSymbolAddress((void**)&p_P2, g_P2);
    cudaGetSymbolAddress((void**)&p_apart, g_apart);

    cudaFuncSetAttribute(gemm_qkv_kernel, cudaFuncAttributeMaxDynamicSharedMemorySize, GSMEM);
    cudaFuncSetAttribute(gemm_single_kernel, cudaFuncAttributeMaxDynamicSharedMemorySize, GSMEM);
    cudaFuncSetAttribute(gemm_gate_kernel, cudaFuncAttributeMaxDynamicSharedMemorySize, GSMEM);

    rmsnorm_half_kernel<<<32, 256>>>(x, anw, p_xh);
    gemm_qkv_kernel<<<dim3(24, 12), 256, GSMEM>>>(p_xh, wq, wk, wv, p_P1);
    reduce_qkv_rope_kernel<<<48, 256>>>(p_P1, fcos, fsin, p_q, p_knew, p_vnew, 12);
    attn_part_kernel<<<dim3(8, 32, NCH), 256>>>(cachek, cachev, p_q, p_knew, p_vnew, p_apart);
    attn_combine_kernel<<<dim3(8, 32), 128>>>(p_apart, p_aoh);
    gemm_single_kernel<<<dim3(16, 16), 256, GSMEM>>>(p_aoh, 4096, wo, 4096, p_P1, 4096, 16);
    reduce_addres_kernel<<<128, 256>>>(p_P1, x, p_res2, 4096, 16);
    rmsnorm_half_kernel<<<32, 256>>>(p_res2, fnw, p_h2h);
    gemm_gate_kernel<<<dim3(86, 3), 256, GSMEM>>>(p_h2h, w1, w3, p_P1, p_P2);
    reduce_gate_kernel<<<86, 256>>>(p_P1, p_P2, p_gh, 3);
    gemm_single_kernel<<<dim3(16, 18), 256, GSMEM>>>(p_gh, 11008, w2, 4096, p_P1, 4096, 18);
    reduce_addres_kernel<<<128, 256>>>(p_P1, p_res2, out, 4096, 18);
}